// round 1
// baseline (speedup 1.0000x reference)
#include <cuda_runtime.h>
#include <cuda_bf16.h>
#include <cstdint>

// ---------------------------------------------------------------------------
// Problem constants
// ---------------------------------------------------------------------------
#define BATCH     4
#define SEQ       2048
#define DMODEL    1024
#define NHEADS    16
#define HDIM      64
#define QKVROW    (3 * DMODEL)          // 3072
#define M_TOKENS  (BATCH * SEQ)         // 8192

// Scratch (device globals: allocation-free per harness rules)
__device__ float g_qkv [ (size_t)M_TOKENS * QKVROW ];   // ~100.7 MB
__device__ float g_attn[ (size_t)M_TOKENS * DMODEL ];   // ~33.6 MB

// ---------------------------------------------------------------------------
// SGEMM with bias: C[M,N] = A[M,K] @ B[K,N] + bias[N]
// 128x128 tile, BK=8, 256 threads, 8x8 per thread
// ---------------------------------------------------------------------------
__global__ __launch_bounds__(256)
void sgemm_bias_kernel(const float* __restrict__ A,
                       const float* __restrict__ B,
                       const float* __restrict__ bias,
                       float* __restrict__ C,
                       int M, int N, int K)
{
    __shared__ float As[8][128];   // transposed: As[k][m]
    __shared__ float Bs[8][128];

    const int tid = threadIdx.x;
    const int tx  = tid & 15;      // 0..15  (N direction)
    const int ty  = tid >> 4;      // 0..15  (M direction)

    const int rowBase = blockIdx.y * 128;
    const int colBase = blockIdx.x * 128;

    // global load mapping
    const int aRow = tid >> 1;            // 0..127
    const int aCol = (tid & 1) << 2;      // 0 or 4
    const int bRow = tid >> 5;            // 0..7
    const int bCol = (tid & 31) << 2;     // 0..124

    const float* Aptr = A + (size_t)(rowBase + aRow) * K + aCol;
    const float* Bptr = B + (size_t)bRow * N + colBase + bCol;

    float acc[8][8];
    #pragma unroll
    for (int i = 0; i < 8; i++)
        #pragma unroll
        for (int j = 0; j < 8; j++) acc[i][j] = 0.0f;

    for (int k0 = 0; k0 < K; k0 += 8) {
        float4 a  = *(const float4*)Aptr;  Aptr += 8;
        float4 b4 = *(const float4*)Bptr;  Bptr += (size_t)8 * N;

        As[aCol + 0][aRow] = a.x;
        As[aCol + 1][aRow] = a.y;
        As[aCol + 2][aRow] = a.z;
        As[aCol + 3][aRow] = a.w;
        *(float4*)&Bs[bRow][bCol] = b4;
        __syncthreads();

        #pragma unroll
        for (int kk = 0; kk < 8; kk++) {
            float4 a0 = *(const float4*)&As[kk][ty * 8];
            float4 a1 = *(const float4*)&As[kk][ty * 8 + 4];
            float4 b0 = *(const float4*)&Bs[kk][tx * 8];
            float4 b1 = *(const float4*)&Bs[kk][tx * 8 + 4];
            float ar[8] = {a0.x, a0.y, a0.z, a0.w, a1.x, a1.y, a1.z, a1.w};
            float br[8] = {b0.x, b0.y, b0.z, b0.w, b1.x, b1.y, b1.z, b1.w};
            #pragma unroll
            for (int i = 0; i < 8; i++)
                #pragma unroll
                for (int j = 0; j < 8; j++)
                    acc[i][j] = fmaf(ar[i], br[j], acc[i][j]);
        }
        __syncthreads();
    }

    // epilogue: add bias, write float4s
    #pragma unroll
    for (int i = 0; i < 8; i++) {
        const int row = rowBase + ty * 8 + i;
        float* crow = C + (size_t)row * N + colBase + tx * 8;
        const float* brow = bias + colBase + tx * 8;
        float4 o0, o1;
        o0.x = acc[i][0] + brow[0];
        o0.y = acc[i][1] + brow[1];
        o0.z = acc[i][2] + brow[2];
        o0.w = acc[i][3] + brow[3];
        o1.x = acc[i][4] + brow[4];
        o1.y = acc[i][5] + brow[5];
        o1.z = acc[i][6] + brow[6];
        o1.w = acc[i][7] + brow[7];
        *(float4*)crow       = o0;
        *(float4*)(crow + 4) = o1;
    }
}

// ---------------------------------------------------------------------------
// Flash attention (fp32, online softmax)
// Grid: (SEQ/64, NHEADS, BATCH). Block: 256 threads.
// Per block: 64 query rows x full 2048 keys in 64-key tiles.
// Thread (ty,tx): score cols = {tx+16c}, out cols = {4tx..4tx+3}, rows = 4ty..
// K tile stored with rotation swizzle (d+key)&63 -> conflict-free QK^T reads.
// P reuses K's buffer with the same rotation.
// ---------------------------------------------------------------------------
__global__ __launch_bounds__(256)
void flash_kernel(const float* __restrict__ qkv, float* __restrict__ attn_out)
{
    __shared__ float Qs [64 * 64];   // 16 KB, unswizzled (reads are broadcast)
    __shared__ float KPs[64 * 64];   // 16 KB, rotation-swizzled; K then P
    __shared__ float Vs [64 * 64];   // 16 KB, unswizzled (float4 reads)

    const int tid = threadIdx.x;
    const int tx  = tid & 15;
    const int ty  = tid >> 4;
    const int r0  = ty * 4;

    const int b  = blockIdx.z;
    const int h  = blockIdx.y;
    const int q0 = blockIdx.x * 64;

    const float scale = 0.125f;   // 1/sqrt(64)

    // qkv layout: [B, S, H, 192]; row stride for fixed (b,h) over s = 16*192 = 3072
    const float* base = qkv + ((size_t)b * SEQ * NHEADS + h) * 192;

    // ---- load Q tile (scaled) ----
    for (int i = tid; i < 64 * 16; i += 256) {
        const int r  = i >> 4;
        const int dq = (i & 15) << 2;
        float4 v = *(const float4*)(base + (size_t)(q0 + r) * 3072 + dq);
        v.x *= scale; v.y *= scale; v.z *= scale; v.w *= scale;
        *(float4*)&Qs[r * 64 + dq] = v;
    }

    float m_i[4], l_i[4], acc[4][4];
    #pragma unroll
    for (int r = 0; r < 4; r++) {
        m_i[r] = -1e30f; l_i[r] = 0.0f;
        #pragma unroll
        for (int c = 0; c < 4; c++) acc[r][c] = 0.0f;
    }

    for (int j0 = 0; j0 < SEQ; j0 += 64) {
        __syncthreads();  // guards Q on iter 0; guards P/V reuse afterwards

        // ---- load K (rotated) and V tiles ----
        for (int i = tid; i < 64 * 16; i += 256) {
            const int r  = i >> 4;
            const int dq = (i & 15) << 2;
            const float* krow = base + (size_t)(j0 + r) * 3072 + HDIM;
            float4 kv = *(const float4*)(krow + dq);
            KPs[r * 64 + ((dq + 0 + r) & 63)] = kv.x;
            KPs[r * 64 + ((dq + 1 + r) & 63)] = kv.y;
            KPs[r * 64 + ((dq + 2 + r) & 63)] = kv.z;
            KPs[r * 64 + ((dq + 3 + r) & 63)] = kv.w;
            float4 vv = *(const float4*)(krow + HDIM + dq);
            *(float4*)&Vs[r * 64 + dq] = vv;
        }
        __syncthreads();

        // ---- S = Q @ K^T (scaled already) ----
        float sv[4][4];
        #pragma unroll
        for (int r = 0; r < 4; r++)
            #pragma unroll
            for (int c = 0; c < 4; c++) sv[r][c] = 0.0f;

        #pragma unroll 8
        for (int d = 0; d < 64; d++) {
            float qf[4], kf[4];
            #pragma unroll
            for (int r = 0; r < 4; r++) qf[r] = Qs[(r0 + r) * 64 + d];
            #pragma unroll
            for (int c = 0; c < 4; c++) {
                const int key = tx + 16 * c;
                kf[c] = KPs[key * 64 + ((d + key) & 63)];
            }
            #pragma unroll
            for (int r = 0; r < 4; r++)
                #pragma unroll
                for (int c = 0; c < 4; c++)
                    sv[r][c] = fmaf(qf[r], kf[c], sv[r][c]);
        }

        // ---- online softmax (reduce over 16 lanes = key cols) ----
        #pragma unroll
        for (int r = 0; r < 4; r++) {
            float m = fmaxf(fmaxf(sv[r][0], sv[r][1]), fmaxf(sv[r][2], sv[r][3]));
            #pragma unroll
            for (int k = 1; k < 16; k <<= 1)
                m = fmaxf(m, __shfl_xor_sync(0xffffffffu, m, k));
            const float mn = fmaxf(m_i[r], m);
            const float alpha = __expf(m_i[r] - mn);
            m_i[r] = mn;
            float s = 0.0f;
            #pragma unroll
            for (int c = 0; c < 4; c++) {
                sv[r][c] = __expf(sv[r][c] - mn);
                s += sv[r][c];
            }
            #pragma unroll
            for (int k = 1; k < 16; k <<= 1)
                s += __shfl_xor_sync(0xffffffffu, s, k);
            l_i[r] = l_i[r] * alpha + s;
            #pragma unroll
            for (int c = 0; c < 4; c++) acc[r][c] *= alpha;
        }

        __syncthreads();   // everyone done reading K before P overwrites it

        // ---- write P into KPs (same rotation) ----
        #pragma unroll
        for (int r = 0; r < 4; r++) {
            const int row = r0 + r;
            #pragma unroll
            for (int c = 0; c < 4; c++) {
                const int key = tx + 16 * c;
                KPs[row * 64 + ((key + row) & 63)] = sv[r][c];
            }
        }
        __syncthreads();

        // ---- acc += P @ V ----
        #pragma unroll 4
        for (int k = 0; k < 64; k++) {
            const float4 vv = *(const float4*)&Vs[k * 64 + tx * 4];
            #pragma unroll
            for (int r = 0; r < 4; r++) {
                const int row = r0 + r;
                const float pf = KPs[row * 64 + ((k + row) & 63)];
                acc[r][0] = fmaf(pf, vv.x, acc[r][0]);
                acc[r][1] = fmaf(pf, vv.y, acc[r][1]);
                acc[r][2] = fmaf(pf, vv.z, acc[r][2]);
                acc[r][3] = fmaf(pf, vv.w, acc[r][3]);
            }
        }
    }

    // ---- epilogue: normalize, write [B,S,D] with head offset ----
    #pragma unroll
    for (int r = 0; r < 4; r++) {
        const float inv = 1.0f / l_i[r];
        float4 o;
        o.x = acc[r][0] * inv;
        o.y = acc[r][1] * inv;
        o.z = acc[r][2] * inv;
        o.w = acc[r][3] * inv;
        const size_t row = (size_t)b * SEQ + q0 + r0 + r;
        *(float4*)&attn_out[row * DMODEL + h * HDIM + tx * 4] = o;
    }
}

// ---------------------------------------------------------------------------
// Launch
// ---------------------------------------------------------------------------
extern "C" void kernel_launch(void* const* d_in, const int* in_sizes, int n_in,
                              void* d_out, int out_size)
{
    const float* x    = (const float*)d_in[0];
    const float* Wqkv = (const float*)d_in[1];
    const float* bqkv = (const float*)d_in[2];
    const float* Wout = (const float*)d_in[3];
    const float* bout = (const float*)d_in[4];
    float* out = (float*)d_out;

    float* qkv  = nullptr;
    float* attn = nullptr;
    cudaGetSymbolAddress((void**)&qkv,  g_qkv);
    cudaGetSymbolAddress((void**)&attn, g_attn);

    // 1) qkv = x @ Wqkv + bqkv      [8192, 3072]
    sgemm_bias_kernel<<<dim3(QKVROW / 128, M_TOKENS / 128), 256>>>(
        x, Wqkv, bqkv, qkv, M_TOKENS, QKVROW, DMODEL);

    // 2) flash attention -> attn    [8192, 1024]
    flash_kernel<<<dim3(SEQ / 64, NHEADS, BATCH), 256>>>(qkv, attn);

    // 3) out = attn @ Wout + bout   [8192, 1024]
    sgemm_bias_kernel<<<dim3(DMODEL / 128, M_TOKENS / 128), 256>>>(
        attn, Wout, bout, out, M_TOKENS, DMODEL, DMODEL);
}

// round 2
// speedup vs baseline: 1.3082x; 1.3082x over previous
#include <cuda_runtime.h>
#include <cuda_bf16.h>
#include <cstdint>

#define BATCH     4
#define SEQ       2048
#define DMODEL    1024
#define NHEADS    16
#define HDIM      64
#define QKVROW    (3 * DMODEL)          // 3072
#define M_TOKENS  (BATCH * SEQ)         // 8192

// Scratch (device globals: allocation-free per harness rules)
__device__ float g_qkv [ (size_t)M_TOKENS * QKVROW ];   // ~100.7 MB
__device__ float g_attn[ (size_t)M_TOKENS * DMODEL ];   // ~33.6 MB

// ---------------------------------------------------------------------------
// packed fp32x2 helpers (sm_103a FFMA2 path)
// ---------------------------------------------------------------------------
__device__ __forceinline__ unsigned long long pack2(float f) {
    unsigned long long r;
    asm("mov.b64 %0, {%1, %1};" : "=l"(r) : "f"(f));
    return r;
}
__device__ __forceinline__ void fma2(unsigned long long& d,
                                     unsigned long long a,
                                     unsigned long long b) {
    asm("fma.rn.f32x2 %0, %1, %2, %0;" : "+l"(d) : "l"(a), "l"(b));
}
__device__ __forceinline__ void mul2(unsigned long long& d, unsigned long long a) {
    asm("mul.rn.f32x2 %0, %0, %1;" : "+l"(d) : "l"(a));
}
__device__ __forceinline__ float lo32(unsigned long long v) {
    return __uint_as_float((unsigned)(v & 0xffffffffu));
}
__device__ __forceinline__ float hi32(unsigned long long v) {
    return __uint_as_float((unsigned)(v >> 32));
}

// ---------------------------------------------------------------------------
// SGEMM with bias: C[M,N] = A[M,K] @ B[K,N] + bias[N]
// 128x128 tile, BK=8, 256 threads, 8x8 per thread, FFMA2, double-buffered smem
// Row pairs packed in accumulators (A-fragment is m-contiguous -> free pairs).
// Column fragment split tx*4 / 64+tx*4 -> conflict-free LDS.128 on B.
// ---------------------------------------------------------------------------
__global__ __launch_bounds__(256)
void sgemm_bias_kernel(const float* __restrict__ A,
                       const float* __restrict__ B,
                       const float* __restrict__ bias,
                       float* __restrict__ C,
                       int M, int N, int K)
{
    __shared__ __align__(16) float As[2][8][128];   // transposed: As[buf][k][m]
    __shared__ __align__(16) float Bs[2][8][128];

    const int tid = threadIdx.x;
    const int tx  = tid & 15;      // N direction
    const int ty  = tid >> 4;      // M direction

    const int rowBase = blockIdx.y * 128;
    const int colBase = blockIdx.x * 128;

    const int aRow = tid >> 1;            // 0..127
    const int aCol = (tid & 1) << 2;      // 0 or 4
    const int bRow = tid >> 5;            // 0..7
    const int bCol = (tid & 31) << 2;     // 0..124

    const float* Aptr = A + (size_t)(rowBase + aRow) * K + aCol;
    const float* Bptr = B + (size_t)bRow * N + colBase + bCol;

    // acc2[i][j]: packed rows (ty*8+2i, ty*8+2i+1); j 0..3 -> cols tx*4+j,
    // j 4..7 -> cols 64+tx*4+(j-4)
    unsigned long long acc2[4][8];
    #pragma unroll
    for (int i = 0; i < 4; i++)
        #pragma unroll
        for (int j = 0; j < 8; j++) acc2[i][j] = 0ULL;

    // preload tile 0
    {
        float4 a = *(const float4*)Aptr;  Aptr += 8;
        float4 b = *(const float4*)Bptr;  Bptr += (size_t)8 * N;
        As[0][aCol + 0][aRow] = a.x;
        As[0][aCol + 1][aRow] = a.y;
        As[0][aCol + 2][aRow] = a.z;
        As[0][aCol + 3][aRow] = a.w;
        *(float4*)&Bs[0][bRow][bCol] = b;
    }
    __syncthreads();

    const int nt = K >> 3;
    for (int t = 0; t < nt; t++) {
        const int cur = t & 1;
        float4 an, bn;
        if (t + 1 < nt) {
            an = *(const float4*)Aptr;  Aptr += 8;
            bn = *(const float4*)Bptr;  Bptr += (size_t)8 * N;
        }

        #pragma unroll
        for (int kk = 0; kk < 8; kk++) {
            const ulonglong2* ap = (const ulonglong2*)&As[cur][kk][ty * 8];
            ulonglong2 a01 = ap[0];
            ulonglong2 a23 = ap[1];
            float4 b0 = *(const float4*)&Bs[cur][kk][tx * 4];
            float4 b1 = *(const float4*)&Bs[cur][kk][64 + tx * 4];
            unsigned long long ar[4] = {a01.x, a01.y, a23.x, a23.y};
            float brf[8] = {b0.x, b0.y, b0.z, b0.w, b1.x, b1.y, b1.z, b1.w};
            #pragma unroll
            for (int j = 0; j < 8; j++) {
                unsigned long long bj = pack2(brf[j]);
                #pragma unroll
                for (int i = 0; i < 4; i++) fma2(acc2[i][j], ar[i], bj);
            }
        }

        if (t + 1 < nt) {
            const int nxt = cur ^ 1;
            As[nxt][aCol + 0][aRow] = an.x;
            As[nxt][aCol + 1][aRow] = an.y;
            As[nxt][aCol + 2][aRow] = an.z;
            As[nxt][aCol + 3][aRow] = an.w;
            *(float4*)&Bs[nxt][bRow][bCol] = bn;
        }
        __syncthreads();
    }

    // epilogue
    #pragma unroll
    for (int i = 0; i < 4; i++) {
        const int rlo = rowBase + ty * 8 + 2 * i;
        #pragma unroll
        for (int half = 0; half < 2; half++) {
            const int cb = colBase + half * 64 + tx * 4;
            float4 olo, ohi;
            float* pl = (float*)&olo;
            float* ph = (float*)&ohi;
            #pragma unroll
            for (int j = 0; j < 4; j++) {
                unsigned long long v = acc2[i][half * 4 + j];
                const float bb = bias[cb + j];
                pl[j] = lo32(v) + bb;
                ph[j] = hi32(v) + bb;
            }
            *(float4*)(C + (size_t)rlo * N + cb)       = olo;
            *(float4*)(C + (size_t)(rlo + 1) * N + cb) = ohi;
        }
    }
}

// ---------------------------------------------------------------------------
// Flash attention (fp32, online softmax), FFMA2 everywhere.
// Grid: (SEQ/64, NHEADS, BATCH). Block: 256 threads.
// KPs buffer holds K then P, both stored with chunk-XOR swizzle:
//   addr(row, d) = row*64 + (((d>>2) ^ (row&15)) << 2) + (d&3)
// -> conflict-free float4 (LDS.128) access in every phase.
// QK^T accumulators packed over d (even/odd halves summed at softmax).
// PV accumulators packed over output-column pairs.
// ---------------------------------------------------------------------------
__global__ __launch_bounds__(256)
void flash_kernel(const float* __restrict__ qkv, float* __restrict__ attn_out)
{
    __shared__ __align__(16) float Qs [64 * 64];
    __shared__ __align__(16) float KPs[64 * 64];
    __shared__ __align__(16) float Vs [64 * 64];

    const int tid = threadIdx.x;
    const int tx  = tid & 15;
    const int ty  = tid >> 4;
    const int r0  = ty * 4;

    const int b  = blockIdx.z;
    const int h  = blockIdx.y;
    const int q0 = blockIdx.x * 64;

    const float scale = 0.125f;   // 1/sqrt(64)

    // qkv layout: [B, S, H, 192]
    const float* base = qkv + ((size_t)b * SEQ * NHEADS + h) * 192;

    // ---- load Q tile (scaled), plain layout ----
    for (int i = tid; i < 64 * 16; i += 256) {
        const int r  = i >> 4;
        const int dq = (i & 15) << 2;
        float4 v = *(const float4*)(base + (size_t)(q0 + r) * 3072 + dq);
        v.x *= scale; v.y *= scale; v.z *= scale; v.w *= scale;
        *(float4*)&Qs[r * 64 + dq] = v;
    }

    float m_i[4], l_i[4];
    unsigned long long acc2[4][2];
    #pragma unroll
    for (int r = 0; r < 4; r++) {
        m_i[r] = -1e30f; l_i[r] = 0.0f;
        acc2[r][0] = 0ULL; acc2[r][1] = 0ULL;
    }

    for (int j0 = 0; j0 < SEQ; j0 += 64) {
        __syncthreads();  // prev-iter P/V reads done before overwrite (also Q on iter 0)

        // ---- load K (XOR-swizzled) and V (plain) ----
        for (int i = tid; i < 64 * 16; i += 256) {
            const int r  = i >> 4;
            const int dq = (i & 15) << 2;
            const float* krow = base + (size_t)(j0 + r) * 3072 + HDIM;
            float4 kv = *(const float4*)(krow + dq);
            *(float4*)&KPs[r * 64 + ((((dq >> 2) ^ (r & 15)) << 2))] = kv;
            float4 vv = *(const float4*)(krow + HDIM + dq);
            *(float4*)&Vs[r * 64 + dq] = vv;
        }
        __syncthreads();

        // ---- S = Q @ K^T, packed over d ----
        unsigned long long sv2[4][4];
        #pragma unroll
        for (int r = 0; r < 4; r++)
            #pragma unroll
            for (int c = 0; c < 4; c++) sv2[r][c] = 0ULL;

        #pragma unroll 2
        for (int d = 0; d < 64; d += 4) {
            ulonglong2 q2[4], k2[4];
            #pragma unroll
            for (int r = 0; r < 4; r++)
                q2[r] = *(const ulonglong2*)&Qs[(r0 + r) * 64 + d];
            #pragma unroll
            for (int c = 0; c < 4; c++) {
                const int key = tx + 16 * c;
                k2[c] = *(const ulonglong2*)&KPs[key * 64 + (((d >> 2) ^ (key & 15)) << 2)];
            }
            #pragma unroll
            for (int r = 0; r < 4; r++)
                #pragma unroll
                for (int c = 0; c < 4; c++) {
                    fma2(sv2[r][c], q2[r].x, k2[c].x);
                    fma2(sv2[r][c], q2[r].y, k2[c].y);
                }
        }

        // ---- unpack scores + online softmax ----
        float sv[4][4];
        #pragma unroll
        for (int r = 0; r < 4; r++)
            #pragma unroll
            for (int c = 0; c < 4; c++)
                sv[r][c] = lo32(sv2[r][c]) + hi32(sv2[r][c]);

        #pragma unroll
        for (int r = 0; r < 4; r++) {
            float m = fmaxf(fmaxf(sv[r][0], sv[r][1]), fmaxf(sv[r][2], sv[r][3]));
            #pragma unroll
            for (int k = 1; k < 16; k <<= 1)
                m = fmaxf(m, __shfl_xor_sync(0xffffffffu, m, k));
            const float mn    = fmaxf(m_i[r], m);
            const float alpha = __expf(m_i[r] - mn);
            m_i[r] = mn;
            float s = 0.0f;
            #pragma unroll
            for (int c = 0; c < 4; c++) {
                sv[r][c] = __expf(sv[r][c] - mn);
                s += sv[r][c];
            }
            #pragma unroll
            for (int k = 1; k < 16; k <<= 1)
                s += __shfl_xor_sync(0xffffffffu, s, k);
            l_i[r] = l_i[r] * alpha + s;
            const unsigned long long a2 = pack2(alpha);
            mul2(acc2[r][0], a2);
            mul2(acc2[r][1], a2);
        }

        __syncthreads();   // all K reads done before P overwrites buffer

        // ---- write P (same XOR swizzle; role: row=query, d=key) ----
        #pragma unroll
        for (int r = 0; r < 4; r++) {
            const int row = r0 + r;
            #pragma unroll
            for (int c = 0; c < 4; c++) {
                const int key = tx + 16 * c;
                KPs[row * 64 + ((((key >> 2) ^ (row & 15)) << 2) | (key & 3))] = sv[r][c];
            }
        }
        __syncthreads();

        // ---- acc += P @ V, packed over output-column pairs ----
        #pragma unroll 2
        for (int k = 0; k < 64; k += 4) {
            float4 p4[4];
            #pragma unroll
            for (int r = 0; r < 4; r++) {
                const int row = r0 + r;
                p4[r] = *(const float4*)&KPs[row * 64 + (((k >> 2) ^ (row & 15)) << 2)];
            }
            ulonglong2 v2[4];
            #pragma unroll
            for (int kk = 0; kk < 4; kk++)
                v2[kk] = *(const ulonglong2*)&Vs[(k + kk) * 64 + tx * 4];

            #pragma unroll
            for (int kk = 0; kk < 4; kk++) {
                #pragma unroll
                for (int r = 0; r < 4; r++) {
                    const float pf = ((const float*)&p4[r])[kk];
                    const unsigned long long pr = pack2(pf);
                    fma2(acc2[r][0], pr, v2[kk].x);
                    fma2(acc2[r][1], pr, v2[kk].y);
                }
            }
        }
    }

    // ---- epilogue ----
    #pragma unroll
    for (int r = 0; r < 4; r++) {
        const float inv = 1.0f / l_i[r];
        float4 o;
        o.x = lo32(acc2[r][0]) * inv;
        o.y = hi32(acc2[r][0]) * inv;
        o.z = lo32(acc2[r][1]) * inv;
        o.w = hi32(acc2[r][1]) * inv;
        const size_t row = (size_t)b * SEQ + q0 + r0 + r;
        *(float4*)&attn_out[row * DMODEL + h * HDIM + tx * 4] = o;
    }
}

// ---------------------------------------------------------------------------
// Launch
// ---------------------------------------------------------------------------
extern "C" void kernel_launch(void* const* d_in, const int* in_sizes, int n_in,
                              void* d_out, int out_size)
{
    const float* x    = (const float*)d_in[0];
    const float* Wqkv = (const float*)d_in[1];
    const float* bqkv = (const float*)d_in[2];
    const float* Wout = (const float*)d_in[3];
    const float* bout = (const float*)d_in[4];
    float* out = (float*)d_out;

    float* qkv  = nullptr;
    float* attn = nullptr;
    cudaGetSymbolAddress((void**)&qkv,  g_qkv);
    cudaGetSymbolAddress((void**)&attn, g_attn);

    // 1) qkv = x @ Wqkv + bqkv      [8192, 3072]
    sgemm_bias_kernel<<<dim3(QKVROW / 128, M_TOKENS / 128), 256>>>(
        x, Wqkv, bqkv, qkv, M_TOKENS, QKVROW, DMODEL);

    // 2) flash attention -> attn    [8192, 1024]
    flash_kernel<<<dim3(SEQ / 64, NHEADS, BATCH), 256>>>(qkv, attn);

    // 3) out = attn @ Wout + bout   [8192, 1024]
    sgemm_bias_kernel<<<dim3(DMODEL / 128, M_TOKENS / 128), 256>>>(
        attn, Wout, bout, out, M_TOKENS, DMODEL, DMODEL);
}

// round 4
// speedup vs baseline: 1.7528x; 1.3399x over previous
#include <cuda_runtime.h>
#include <cuda_bf16.h>
#include <cstdint>

#define BATCH     4
#define SEQ       2048
#define DMODEL    1024
#define NHEADS    16
#define HDIM      64
#define QKVROW    (3 * DMODEL)          // 3072
#define M_TOKENS  (BATCH * SEQ)         // 8192

// fp32 scratch
__device__ float g_qkv [ (size_t)M_TOKENS * QKVROW ];
__device__ float g_attn[ (size_t)M_TOKENS * DMODEL ];
// bf16 split planes
__device__ __nv_bfloat16 g_xh [ (size_t)M_TOKENS * DMODEL ];
__device__ __nv_bfloat16 g_xl [ (size_t)M_TOKENS * DMODEL ];
__device__ __nv_bfloat16 g_ah [ (size_t)M_TOKENS * DMODEL ];
__device__ __nv_bfloat16 g_al [ (size_t)M_TOKENS * DMODEL ];
__device__ __nv_bfloat16 g_w1h[ (size_t)QKVROW * DMODEL ];   // Wqkv^T [N,K]
__device__ __nv_bfloat16 g_w1l[ (size_t)QKVROW * DMODEL ];
__device__ __nv_bfloat16 g_w2h[ (size_t)DMODEL * DMODEL ];   // Wout^T [N,K]
__device__ __nv_bfloat16 g_w2l[ (size_t)DMODEL * DMODEL ];

// ---------------------------------------------------------------------------
// helpers
// ---------------------------------------------------------------------------
__device__ __forceinline__ uint32_t smem_u32(const void* p) {
    uint32_t a;
    asm("{ .reg .u64 t; cvta.to.shared.u64 t, %1; cvt.u32.u64 %0, t; }" : "=r"(a) : "l"(p));
    return a;
}

#define CP_ASYNC16(dst, src) \
    asm volatile("cp.async.cg.shared.global [%0], [%1], 16;" :: "r"(dst), "l"(src))
#define CP_COMMIT()  asm volatile("cp.async.commit_group;" ::: "memory")
#define CP_WAIT0()   asm volatile("cp.async.wait_group 0;" ::: "memory")
#define CP_WAIT1()   asm volatile("cp.async.wait_group 1;" ::: "memory")

#define LDSM_X4(r0, r1, r2, r3, addr) \
    asm volatile("ldmatrix.sync.aligned.m8n8.x4.shared.b16 {%0,%1,%2,%3}, [%4];" \
        : "=r"(r0), "=r"(r1), "=r"(r2), "=r"(r3) : "r"(addr))

#define MMA_BF16(d, a, b0, b1) \
    asm volatile("mma.sync.aligned.m16n8k16.row.col.f32.bf16.bf16.f32 " \
        "{%0,%1,%2,%3}, {%4,%5,%6,%7}, {%8,%9}, {%0,%1,%2,%3};" \
        : "+f"((d)[0]), "+f"((d)[1]), "+f"((d)[2]), "+f"((d)[3]) \
        : "r"((a)[0]), "r"((a)[1]), "r"((a)[2]), "r"((a)[3]), "r"(b0), "r"(b1))

// packed fp32x2 (flash)
__device__ __forceinline__ unsigned long long pack2(float f) {
    unsigned long long r;
    asm("mov.b64 %0, {%1, %1};" : "=l"(r) : "f"(f));
    return r;
}
__device__ __forceinline__ void fma2(unsigned long long& d,
                                     unsigned long long a,
                                     unsigned long long b) {
    asm("fma.rn.f32x2 %0, %1, %2, %0;" : "+l"(d) : "l"(a), "l"(b));
}
__device__ __forceinline__ void mul2(unsigned long long& d, unsigned long long a) {
    asm("mul.rn.f32x2 %0, %0, %1;" : "+l"(d) : "l"(a));
}
__device__ __forceinline__ float lo32(unsigned long long v) {
    return __uint_as_float((unsigned)(v & 0xffffffffu));
}
__device__ __forceinline__ float hi32(unsigned long long v) {
    return __uint_as_float((unsigned)(v >> 32));
}

// ---------------------------------------------------------------------------
// Split kernels: fp32 -> (hi, lo) bf16 planes
// ---------------------------------------------------------------------------
__global__ __launch_bounds__(256)
void split_plain(const float* __restrict__ in,
                 __nv_bfloat16* __restrict__ h,
                 __nv_bfloat16* __restrict__ l)
{
    const size_t i8 = ((size_t)blockIdx.x * 256 + threadIdx.x) * 8;
    float4 a = *(const float4*)(in + i8);
    float4 b = *(const float4*)(in + i8 + 4);
    __nv_bfloat16 hh[8], ll[8];
    const float* f = (const float*)&a;
    #pragma unroll
    for (int j = 0; j < 4; j++) {
        hh[j] = __float2bfloat16(f[j]);
        ll[j] = __float2bfloat16(f[j] - __bfloat162float(hh[j]));
    }
    f = (const float*)&b;
    #pragma unroll
    for (int j = 0; j < 4; j++) {
        hh[4 + j] = __float2bfloat16(f[j]);
        ll[4 + j] = __float2bfloat16(f[j] - __bfloat162float(hh[4 + j]));
    }
    *(uint4*)(h + i8) = *(const uint4*)hh;
    *(uint4*)(l + i8) = *(const uint4*)ll;
}

// W [K,N] fp32 -> Wh^T, Wl^T [N,K] bf16 (transposed)
__global__ __launch_bounds__(256)
void split_transpose(const float* __restrict__ W,
                     __nv_bfloat16* __restrict__ Th,
                     __nv_bfloat16* __restrict__ Tl,
                     int K, int N)
{
    __shared__ float s[32][33];
    const int k0 = blockIdx.x * 32;
    const int n0 = blockIdx.y * 32;
    const int tx = threadIdx.x;
    const int ty = threadIdx.y;
    #pragma unroll
    for (int i = 0; i < 4; i++)
        s[ty + 8 * i][tx] = W[(size_t)(k0 + ty + 8 * i) * N + n0 + tx];
    __syncthreads();
    #pragma unroll
    for (int i = 0; i < 4; i++) {
        const float v = s[tx][ty + 8 * i];
        const __nv_bfloat16 h = __float2bfloat16(v);
        const __nv_bfloat16 l = __float2bfloat16(v - __bfloat162float(h));
        const size_t o = (size_t)(n0 + ty + 8 * i) * K + k0 + tx;
        Th[o] = h;
        Tl[o] = l;
    }
}

// ---------------------------------------------------------------------------
// HMMA bf16 split-2 GEMM: C[M,N] = A@W + bias
// A planes [M,K] row-major, B planes = W^T [N,K] (col-major KxN for mma).
// 128x128 block tile, BK=32, 256 threads, warps 2(M)x4(N) -> 64x32 per warp.
// Smem: 64-byte rows, chunk-XOR swizzle c ^ ((row>>1)&3), double buffered.
// ---------------------------------------------------------------------------
#define HSMEM_BUF   32768                         // Ah 8K | Al 8K | Bh 8K | Bl 8K
#define HSMEM_TOTAL (2 * HSMEM_BUF)

__global__ __launch_bounds__(256)
void gemm_hmma(const __nv_bfloat16* __restrict__ Ah,
               const __nv_bfloat16* __restrict__ Al,
               const __nv_bfloat16* __restrict__ Bh,
               const __nv_bfloat16* __restrict__ Bl,
               const float* __restrict__ bias,
               float* __restrict__ C,
               int M, int N, int K)
{
    extern __shared__ __align__(128) char smem[];
    const uint32_t smb = smem_u32(smem);
    const int tid  = threadIdx.x;
    const int wid  = tid >> 5;
    const int lane = tid & 31;
    const int wm   = wid >> 2;       // 0..1  (64 rows each)
    const int wn   = wid & 3;        // 0..3  (32 cols each)

    const int m0 = blockIdx.y * 128;
    const int n0 = blockIdx.x * 128;

    float acc[4][4][4];
    #pragma unroll
    for (int i = 0; i < 4; i++)
        #pragma unroll
        for (int j = 0; j < 4; j++)
            #pragma unroll
            for (int q = 0; q < 4; q++) acc[i][j][q] = 0.0f;

    // per-lane ldmatrix addressing components
    const int a_row16 = lane & 15;        // row within 16-row tile
    const int a_half  = lane >> 4;        // k-chunk half (0/1)
    const int b_n16   = (lane & 7) + ((lane >> 4) << 3);   // n within 16 (two n8 tiles)
    const int b_half  = (lane >> 3) & 1;  // k-chunk half

    // ---- cp.async tile loader: 4 planes, 128 rows x 64B each ----
    auto issue = [&](int buf, int kc) {
        #pragma unroll
        for (int p = 0; p < 2; p++) {
            const int idx = tid + p * 256;        // 0..511
            const int row = idx >> 2;             // 0..127
            const int c   = idx & 3;              // 16B chunk
            const uint32_t soff = buf * HSMEM_BUF + row * 64 +
                                  ((c ^ ((row >> 1) & 3)) << 4);
            const size_t ga = (size_t)(m0 + row) * K + kc + c * 8;
            const size_t gb = (size_t)(n0 + row) * K + kc + c * 8;
            CP_ASYNC16(smb + soff,         (const void*)(Ah + ga));
            CP_ASYNC16(smb + soff + 8192,  (const void*)(Al + ga));
            CP_ASYNC16(smb + soff + 16384, (const void*)(Bh + gb));
            CP_ASYNC16(smb + soff + 24576, (const void*)(Bl + gb));
        }
    };

    auto compute = [&](int buf) {
        const uint32_t sa = smb + buf * HSMEM_BUF;
        #pragma unroll
        for (int s = 0; s < 2; s++) {
            uint32_t ah[4][4], al[4][4];
            #pragma unroll
            for (int mt = 0; mt < 4; mt++) {
                const int row = wm * 64 + mt * 16 + a_row16;
                const int c   = 2 * s + a_half;
                const uint32_t ad = sa + row * 64 + ((c ^ ((row >> 1) & 3)) << 4);
                LDSM_X4(ah[mt][0], ah[mt][1], ah[mt][2], ah[mt][3], ad);
                LDSM_X4(al[mt][0], al[mt][1], al[mt][2], al[mt][3], ad + 8192);
            }
            uint32_t bh[2][4], bl[2][4];
            #pragma unroll
            for (int np = 0; np < 2; np++) {
                const int n = wn * 32 + np * 16 + b_n16;
                const int c = 2 * s + b_half;
                const uint32_t bd = sa + 16384 + n * 64 + ((c ^ ((n >> 1) & 3)) << 4);
                LDSM_X4(bh[np][0], bh[np][1], bh[np][2], bh[np][3], bd);
                LDSM_X4(bl[np][0], bl[np][1], bl[np][2], bl[np][3], bd + 8192);
            }
            #pragma unroll
            for (int mt = 0; mt < 4; mt++)
                #pragma unroll
                for (int nt = 0; nt < 4; nt++) {
                    const uint32_t b0h = bh[nt >> 1][(nt & 1) * 2];
                    const uint32_t b1h = bh[nt >> 1][(nt & 1) * 2 + 1];
                    const uint32_t b0l = bl[nt >> 1][(nt & 1) * 2];
                    const uint32_t b1l = bl[nt >> 1][(nt & 1) * 2 + 1];
                    MMA_BF16(acc[mt][nt], ah[mt], b0h, b1h);
                    MMA_BF16(acc[mt][nt], ah[mt], b0l, b1l);
                    MMA_BF16(acc[mt][nt], al[mt], b0h, b1h);
                }
        }
    };

    issue(0, 0);
    CP_COMMIT();
    const int nchunks = K >> 5;                // K/32
    for (int t = 0; t < nchunks; t++) {
        if (t + 1 < nchunks) {
            issue((t + 1) & 1, (t + 1) * 32);
            CP_COMMIT();
            CP_WAIT1();
        } else {
            CP_WAIT0();
        }
        __syncthreads();
        compute(t & 1);
        __syncthreads();
    }

    // ---- epilogue ----
    const int er = lane >> 2;
    const int ec = (lane & 3) * 2;
    #pragma unroll
    for (int mt = 0; mt < 4; mt++)
        #pragma unroll
        for (int nt = 0; nt < 4; nt++) {
            const int row = m0 + wm * 64 + mt * 16 + er;
            const int col = n0 + wn * 32 + nt * 8 + ec;
            const float b0 = bias[col];
            const float b1 = bias[col + 1];
            float2 v0 = make_float2(acc[mt][nt][0] + b0, acc[mt][nt][1] + b1);
            float2 v1 = make_float2(acc[mt][nt][2] + b0, acc[mt][nt][3] + b1);
            *(float2*)(C + (size_t)row * N + col)       = v0;
            *(float2*)(C + (size_t)(row + 8) * N + col) = v1;
        }
}

// ---------------------------------------------------------------------------
// Flash attention (fp32, online softmax), FFMA2 — unchanged
// ---------------------------------------------------------------------------
__global__ __launch_bounds__(256)
void flash_kernel(const float* __restrict__ qkv, float* __restrict__ attn_out)
{
    __shared__ __align__(16) float Qs [64 * 64];
    __shared__ __align__(16) float KPs[64 * 64];
    __shared__ __align__(16) float Vs [64 * 64];

    const int tid = threadIdx.x;
    const int tx  = tid & 15;
    const int ty  = tid >> 4;
    const int r0  = ty * 4;

    const int b  = blockIdx.z;
    const int h  = blockIdx.y;
    const int q0 = blockIdx.x * 64;

    const float scale = 0.125f;

    const float* base = qkv + ((size_t)b * SEQ * NHEADS + h) * 192;

    for (int i = tid; i < 64 * 16; i += 256) {
        const int r  = i >> 4;
        const int dq = (i & 15) << 2;
        float4 v = *(const float4*)(base + (size_t)(q0 + r) * 3072 + dq);
        v.x *= scale; v.y *= scale; v.z *= scale; v.w *= scale;
        *(float4*)&Qs[r * 64 + dq] = v;
    }

    float m_i[4], l_i[4];
    unsigned long long acc2[4][2];
    #pragma unroll
    for (int r = 0; r < 4; r++) {
        m_i[r] = -1e30f; l_i[r] = 0.0f;
        acc2[r][0] = 0ULL; acc2[r][1] = 0ULL;
    }

    for (int j0 = 0; j0 < SEQ; j0 += 64) {
        __syncthreads();

        for (int i = tid; i < 64 * 16; i += 256) {
            const int r  = i >> 4;
            const int dq = (i & 15) << 2;
            const float* krow = base + (size_t)(j0 + r) * 3072 + HDIM;
            float4 kv = *(const float4*)(krow + dq);
            *(float4*)&KPs[r * 64 + ((((dq >> 2) ^ (r & 15)) << 2))] = kv;
            float4 vv = *(const float4*)(krow + HDIM + dq);
            *(float4*)&Vs[r * 64 + dq] = vv;
        }
        __syncthreads();

        unsigned long long sv2[4][4];
        #pragma unroll
        for (int r = 0; r < 4; r++)
            #pragma unroll
            for (int c = 0; c < 4; c++) sv2[r][c] = 0ULL;

        #pragma unroll 2
        for (int d = 0; d < 64; d += 4) {
            ulonglong2 q2[4], k2[4];
            #pragma unroll
            for (int r = 0; r < 4; r++)
                q2[r] = *(const ulonglong2*)&Qs[(r0 + r) * 64 + d];
            #pragma unroll
            for (int c = 0; c < 4; c++) {
                const int key = tx + 16 * c;
                k2[c] = *(const ulonglong2*)&KPs[key * 64 + (((d >> 2) ^ (key & 15)) << 2)];
            }
            #pragma unroll
            for (int r = 0; r < 4; r++)
                #pragma unroll
                for (int c = 0; c < 4; c++) {
                    fma2(sv2[r][c], q2[r].x, k2[c].x);
                    fma2(sv2[r][c], q2[r].y, k2[c].y);
                }
        }

        float sv[4][4];
        #pragma unroll
        for (int r = 0; r < 4; r++)
            #pragma unroll
            for (int c = 0; c < 4; c++)
                sv[r][c] = lo32(sv2[r][c]) + hi32(sv2[r][c]);

        #pragma unroll
        for (int r = 0; r < 4; r++) {
            float m = fmaxf(fmaxf(sv[r][0], sv[r][1]), fmaxf(sv[r][2], sv[r][3]));
            #pragma unroll
            for (int k = 1; k < 16; k <<= 1)
                m = fmaxf(m, __shfl_xor_sync(0xffffffffu, m, k));
            const float mn    = fmaxf(m_i[r], m);
            const float alpha = __expf(m_i[r] - mn);
            m_i[r] = mn;
            float s = 0.0f;
            #pragma unroll
            for (int c = 0; c < 4; c++) {
                sv[r][c] = __expf(sv[r][c] - mn);
                s += sv[r][c];
            }
            #pragma unroll
            for (int k = 1; k < 16; k <<= 1)
                s += __shfl_xor_sync(0xffffffffu, s, k);
            l_i[r] = l_i[r] * alpha + s;
            const unsigned long long a2 = pack2(alpha);
            mul2(acc2[r][0], a2);
            mul2(acc2[r][1], a2);
        }

        __syncthreads();

        #pragma unroll
        for (int r = 0; r < 4; r++) {
            const int row = r0 + r;
            #pragma unroll
            for (int c = 0; c < 4; c++) {
                const int key = tx + 16 * c;
                KPs[row * 64 + ((((key >> 2) ^ (row & 15)) << 2) | (key & 3))] = sv[r][c];
            }
        }
        __syncthreads();

        #pragma unroll 2
        for (int k = 0; k < 64; k += 4) {
            float4 p4[4];
            #pragma unroll
            for (int r = 0; r < 4; r++) {
                const int row = r0 + r;
                p4[r] = *(const float4*)&KPs[row * 64 + (((k >> 2) ^ (row & 15)) << 2)];
            }
            ulonglong2 v2[4];
            #pragma unroll
            for (int kk = 0; kk < 4; kk++)
                v2[kk] = *(const ulonglong2*)&Vs[(k + kk) * 64 + tx * 4];

            #pragma unroll
            for (int kk = 0; kk < 4; kk++) {
                #pragma unroll
                for (int r = 0; r < 4; r++) {
                    const float pf = ((const float*)&p4[r])[kk];
                    const unsigned long long pr = pack2(pf);
                    fma2(acc2[r][0], pr, v2[kk].x);
                    fma2(acc2[r][1], pr, v2[kk].y);
                }
            }
        }
    }

    #pragma unroll
    for (int r = 0; r < 4; r++) {
        const float inv = 1.0f / l_i[r];
        float4 o;
        o.x = lo32(acc2[r][0]) * inv;
        o.y = hi32(acc2[r][0]) * inv;
        o.z = lo32(acc2[r][1]) * inv;
        o.w = hi32(acc2[r][1]) * inv;
        const size_t row = (size_t)b * SEQ + q0 + r0 + r;
        *(float4*)&attn_out[row * DMODEL + h * HDIM + tx * 4] = o;
    }
}

// ---------------------------------------------------------------------------
// Launch
// ---------------------------------------------------------------------------
extern "C" void kernel_launch(void* const* d_in, const int* in_sizes, int n_in,
                              void* d_out, int out_size)
{
    const float* x    = (const float*)d_in[0];
    const float* Wqkv = (const float*)d_in[1];
    const float* bqkv = (const float*)d_in[2];
    const float* Wout = (const float*)d_in[3];
    const float* bout = (const float*)d_in[4];
    float* out = (float*)d_out;

    float *qkv, *attn;
    __nv_bfloat16 *xh, *xl, *ah, *al, *w1h, *w1l, *w2h, *w2l;
    cudaGetSymbolAddress((void**)&qkv,  g_qkv);
    cudaGetSymbolAddress((void**)&attn, g_attn);
    cudaGetSymbolAddress((void**)&xh,  g_xh);
    cudaGetSymbolAddress((void**)&xl,  g_xl);
    cudaGetSymbolAddress((void**)&ah,  g_ah);
    cudaGetSymbolAddress((void**)&al,  g_al);
    cudaGetSymbolAddress((void**)&w1h, g_w1h);
    cudaGetSymbolAddress((void**)&w1l, g_w1l);
    cudaGetSymbolAddress((void**)&w2h, g_w2h);
    cudaGetSymbolAddress((void**)&w2l, g_w2l);

    cudaFuncSetAttribute(gemm_hmma, cudaFuncAttributeMaxDynamicSharedMemorySize,
                         HSMEM_TOTAL);

    // splits
    split_plain<<<(M_TOKENS * DMODEL) / (256 * 8), 256>>>(x, xh, xl);
    split_transpose<<<dim3(DMODEL / 32, QKVROW / 32), dim3(32, 8)>>>(
        Wqkv, w1h, w1l, DMODEL, QKVROW);
    split_transpose<<<dim3(DMODEL / 32, DMODEL / 32), dim3(32, 8)>>>(
        Wout, w2h, w2l, DMODEL, DMODEL);

    // 1) qkv = x @ Wqkv + bqkv
    gemm_hmma<<<dim3(QKVROW / 128, M_TOKENS / 128), 256, HSMEM_TOTAL>>>(
        xh, xl, w1h, w1l, bqkv, qkv, M_TOKENS, QKVROW, DMODEL);

    // 2) flash attention
    flash_kernel<<<dim3(SEQ / 64, NHEADS, BATCH), 256>>>(qkv, attn);

    // 3) split attn, out = attn @ Wout + bout
    split_plain<<<(M_TOKENS * DMODEL) / (256 * 8), 256>>>(attn, ah, al);
    gemm_hmma<<<dim3(DMODEL / 128, M_TOKENS / 128), 256, HSMEM_TOTAL>>>(
        ah, al, w2h, w2l, bout, out, M_TOKENS, DMODEL, DMODEL);
}

// round 5
// speedup vs baseline: 4.1205x; 2.3508x over previous
#include <cuda_runtime.h>
#include <cuda_bf16.h>
#include <cstdint>

#define BATCH     4
#define SEQ       2048
#define DMODEL    1024
#define NHEADS    16
#define HDIM      64
#define QKVROW    (3 * DMODEL)          // 3072
#define M_TOKENS  (BATCH * SEQ)         // 8192

// bf16 plane scratch (allocation-free per harness rules)
__device__ __nv_bfloat16 g_xh [ (size_t)M_TOKENS * DMODEL ];
__device__ __nv_bfloat16 g_xl [ (size_t)M_TOKENS * DMODEL ];
__device__ __nv_bfloat16 g_qh [ (size_t)M_TOKENS * QKVROW ];  // qkv hi plane
__device__ __nv_bfloat16 g_ql [ (size_t)M_TOKENS * QKVROW ];  // qkv lo plane
__device__ __nv_bfloat16 g_ah [ (size_t)M_TOKENS * DMODEL ];  // attn hi
__device__ __nv_bfloat16 g_al [ (size_t)M_TOKENS * DMODEL ];  // attn lo
__device__ __nv_bfloat16 g_w1h[ (size_t)QKVROW * DMODEL ];    // Wqkv^T [N,K]
__device__ __nv_bfloat16 g_w1l[ (size_t)QKVROW * DMODEL ];
__device__ __nv_bfloat16 g_w2h[ (size_t)DMODEL * DMODEL ];    // Wout^T [N,K]
__device__ __nv_bfloat16 g_w2l[ (size_t)DMODEL * DMODEL ];

// ---------------------------------------------------------------------------
// helpers
// ---------------------------------------------------------------------------
__device__ __forceinline__ uint32_t smem_u32(const void* p) {
    uint32_t a;
    asm("{ .reg .u64 t; cvta.to.shared.u64 t, %1; cvt.u32.u64 %0, t; }" : "=r"(a) : "l"(p));
    return a;
}
__device__ __forceinline__ float ex2f(float x) {
    float y;
    asm("ex2.approx.ftz.f32 %0, %1;" : "=f"(y) : "f"(x));
    return y;
}

#define CP_ASYNC16(dst, src) \
    asm volatile("cp.async.cg.shared.global [%0], [%1], 16;" :: "r"(dst), "l"(src))
#define CP_COMMIT()  asm volatile("cp.async.commit_group;" ::: "memory")
#define CP_WAIT0()   asm volatile("cp.async.wait_group 0;" ::: "memory")
#define CP_WAIT1()   asm volatile("cp.async.wait_group 1;" ::: "memory")

#define LDSM_X4(r0, r1, r2, r3, addr) \
    asm volatile("ldmatrix.sync.aligned.m8n8.x4.shared.b16 {%0,%1,%2,%3}, [%4];" \
        : "=r"(r0), "=r"(r1), "=r"(r2), "=r"(r3) : "r"(addr))
#define LDSM_X4_T(r0, r1, r2, r3, addr) \
    asm volatile("ldmatrix.sync.aligned.m8n8.x4.trans.shared.b16 {%0,%1,%2,%3}, [%4];" \
        : "=r"(r0), "=r"(r1), "=r"(r2), "=r"(r3) : "r"(addr))

#define MMA_BF16(d, a, b0, b1) \
    asm volatile("mma.sync.aligned.m16n8k16.row.col.f32.bf16.bf16.f32 " \
        "{%0,%1,%2,%3}, {%4,%5,%6,%7}, {%8,%9}, {%0,%1,%2,%3};" \
        : "+f"((d)[0]), "+f"((d)[1]), "+f"((d)[2]), "+f"((d)[3]) \
        : "r"((a)[0]), "r"((a)[1]), "r"((a)[2]), "r"((a)[3]), "r"(b0), "r"(b1))

// ---------------------------------------------------------------------------
// Split kernels
// ---------------------------------------------------------------------------
__global__ __launch_bounds__(256)
void split_plain(const float* __restrict__ in,
                 __nv_bfloat16* __restrict__ h,
                 __nv_bfloat16* __restrict__ l)
{
    const size_t i8 = ((size_t)blockIdx.x * 256 + threadIdx.x) * 8;
    float4 a = *(const float4*)(in + i8);
    float4 b = *(const float4*)(in + i8 + 4);
    __nv_bfloat16 hh[8], ll[8];
    const float* f = (const float*)&a;
    #pragma unroll
    for (int j = 0; j < 4; j++) {
        hh[j] = __float2bfloat16(f[j]);
        ll[j] = __float2bfloat16(f[j] - __bfloat162float(hh[j]));
    }
    f = (const float*)&b;
    #pragma unroll
    for (int j = 0; j < 4; j++) {
        hh[4 + j] = __float2bfloat16(f[j]);
        ll[4 + j] = __float2bfloat16(f[j] - __bfloat162float(hh[4 + j]));
    }
    *(uint4*)(h + i8) = *(const uint4*)hh;
    *(uint4*)(l + i8) = *(const uint4*)ll;
}

__global__ __launch_bounds__(256)
void split_transpose(const float* __restrict__ W,
                     __nv_bfloat16* __restrict__ Th,
                     __nv_bfloat16* __restrict__ Tl,
                     int K, int N)
{
    __shared__ float s[32][33];
    const int k0 = blockIdx.x * 32;
    const int n0 = blockIdx.y * 32;
    const int tx = threadIdx.x;
    const int ty = threadIdx.y;
    #pragma unroll
    for (int i = 0; i < 4; i++)
        s[ty + 8 * i][tx] = W[(size_t)(k0 + ty + 8 * i) * N + n0 + tx];
    __syncthreads();
    #pragma unroll
    for (int i = 0; i < 4; i++) {
        const float v = s[tx][ty + 8 * i];
        const __nv_bfloat16 h = __float2bfloat16(v);
        const __nv_bfloat16 l = __float2bfloat16(v - __bfloat162float(h));
        const size_t o = (size_t)(n0 + ty + 8 * i) * K + k0 + tx;
        Th[o] = h;
        Tl[o] = l;
    }
}

// ---------------------------------------------------------------------------
// HMMA bf16 split-2 GEMM: C = A@W + bias. mode 0: fp32 out; mode 1: bf16 planes.
// ---------------------------------------------------------------------------
#define HSMEM_BUF   32768
#define HSMEM_TOTAL (2 * HSMEM_BUF)

__global__ __launch_bounds__(256)
void gemm_hmma(const __nv_bfloat16* __restrict__ Ah,
               const __nv_bfloat16* __restrict__ Al,
               const __nv_bfloat16* __restrict__ Bh,
               const __nv_bfloat16* __restrict__ Bl,
               const float* __restrict__ bias,
               float* __restrict__ C,
               __nv_bfloat16* __restrict__ Ch,
               __nv_bfloat16* __restrict__ Cl,
               int M, int N, int K, int write_bf16)
{
    extern __shared__ __align__(128) char smem[];
    const uint32_t smb = smem_u32(smem);
    const int tid  = threadIdx.x;
    const int wid  = tid >> 5;
    const int lane = tid & 31;
    const int wm   = wid >> 2;
    const int wn   = wid & 3;

    const int m0 = blockIdx.y * 128;
    const int n0 = blockIdx.x * 128;

    float acc[4][4][4];
    #pragma unroll
    for (int i = 0; i < 4; i++)
        #pragma unroll
        for (int j = 0; j < 4; j++)
            #pragma unroll
            for (int q = 0; q < 4; q++) acc[i][j][q] = 0.0f;

    const int a_row16 = lane & 15;
    const int a_half  = lane >> 4;
    const int b_n16   = (lane & 7) + ((lane >> 4) << 3);
    const int b_half  = (lane >> 3) & 1;

    auto issue = [&](int buf, int kc) {
        #pragma unroll
        for (int p = 0; p < 2; p++) {
            const int idx = tid + p * 256;
            const int row = idx >> 2;
            const int c   = idx & 3;
            const uint32_t soff = buf * HSMEM_BUF + row * 64 +
                                  ((c ^ ((row >> 1) & 3)) << 4);
            const size_t ga = (size_t)(m0 + row) * K + kc + c * 8;
            const size_t gb = (size_t)(n0 + row) * K + kc + c * 8;
            CP_ASYNC16(smb + soff,         (const void*)(Ah + ga));
            CP_ASYNC16(smb + soff + 8192,  (const void*)(Al + ga));
            CP_ASYNC16(smb + soff + 16384, (const void*)(Bh + gb));
            CP_ASYNC16(smb + soff + 24576, (const void*)(Bl + gb));
        }
    };

    auto compute = [&](int buf) {
        const uint32_t sa = smb + buf * HSMEM_BUF;
        #pragma unroll
        for (int s = 0; s < 2; s++) {
            uint32_t ah[4][4], al[4][4];
            #pragma unroll
            for (int mt = 0; mt < 4; mt++) {
                const int row = wm * 64 + mt * 16 + a_row16;
                const int c   = 2 * s + a_half;
                const uint32_t ad = sa + row * 64 + ((c ^ ((row >> 1) & 3)) << 4);
                LDSM_X4(ah[mt][0], ah[mt][1], ah[mt][2], ah[mt][3], ad);
                LDSM_X4(al[mt][0], al[mt][1], al[mt][2], al[mt][3], ad + 8192);
            }
            uint32_t bh[2][4], bl[2][4];
            #pragma unroll
            for (int np = 0; np < 2; np++) {
                const int n = wn * 32 + np * 16 + b_n16;
                const int c = 2 * s + b_half;
                const uint32_t bd = sa + 16384 + n * 64 + ((c ^ ((n >> 1) & 3)) << 4);
                LDSM_X4(bh[np][0], bh[np][1], bh[np][2], bh[np][3], bd);
                LDSM_X4(bl[np][0], bl[np][1], bl[np][2], bl[np][3], bd + 8192);
            }
            #pragma unroll
            for (int mt = 0; mt < 4; mt++)
                #pragma unroll
                for (int nt = 0; nt < 4; nt++) {
                    const uint32_t b0h = bh[nt >> 1][(nt & 1) * 2];
                    const uint32_t b1h = bh[nt >> 1][(nt & 1) * 2 + 1];
                    const uint32_t b0l = bl[nt >> 1][(nt & 1) * 2];
                    const uint32_t b1l = bl[nt >> 1][(nt & 1) * 2 + 1];
                    MMA_BF16(acc[mt][nt], ah[mt], b0h, b1h);
                    MMA_BF16(acc[mt][nt], ah[mt], b0l, b1l);
                    MMA_BF16(acc[mt][nt], al[mt], b0h, b1h);
                }
        }
    };

    issue(0, 0);
    CP_COMMIT();
    const int nchunks = K >> 5;
    for (int t = 0; t < nchunks; t++) {
        if (t + 1 < nchunks) {
            issue((t + 1) & 1, (t + 1) * 32);
            CP_COMMIT();
            CP_WAIT1();
        } else {
            CP_WAIT0();
        }
        __syncthreads();
        compute(t & 1);
        __syncthreads();
    }

    const int er = lane >> 2;
    const int ec = (lane & 3) * 2;
    #pragma unroll
    for (int mt = 0; mt < 4; mt++)
        #pragma unroll
        for (int nt = 0; nt < 4; nt++) {
            const int row = m0 + wm * 64 + mt * 16 + er;
            const int col = n0 + wn * 32 + nt * 8 + ec;
            const float b0 = bias[col];
            const float b1 = bias[col + 1];
            const float v00 = acc[mt][nt][0] + b0;
            const float v01 = acc[mt][nt][1] + b1;
            const float v10 = acc[mt][nt][2] + b0;
            const float v11 = acc[mt][nt][3] + b1;
            if (write_bf16) {
                __nv_bfloat162 h0 = __floats2bfloat162_rn(v00, v01);
                float2 hf0 = __bfloat1622float2(h0);
                __nv_bfloat162 l0 = __floats2bfloat162_rn(v00 - hf0.x, v01 - hf0.y);
                __nv_bfloat162 h1 = __floats2bfloat162_rn(v10, v11);
                float2 hf1 = __bfloat1622float2(h1);
                __nv_bfloat162 l1 = __floats2bfloat162_rn(v10 - hf1.x, v11 - hf1.y);
                *(__nv_bfloat162*)(Ch + (size_t)row * N + col)       = h0;
                *(__nv_bfloat162*)(Cl + (size_t)row * N + col)       = l0;
                *(__nv_bfloat162*)(Ch + (size_t)(row + 8) * N + col) = h1;
                *(__nv_bfloat162*)(Cl + (size_t)(row + 8) * N + col) = l1;
            } else {
                *(float2*)(C + (size_t)row * N + col)       = make_float2(v00, v01);
                *(float2*)(C + (size_t)(row + 8) * N + col) = make_float2(v10, v11);
            }
        }
}

// ---------------------------------------------------------------------------
// Flash attention, HMMA bf16 split-2, online softmax in exp2 domain.
// Grid: (SEQ/128, NHEADS, BATCH), 256 threads (8 warps x 16 q rows).
// smem: Q planes 32KB @0, then 2 x 64KB KV buffers (Kh|Kl|Vh|Vl 16KB each).
// ---------------------------------------------------------------------------
#define FSC 0.18033688011112042f     // 0.125 * log2(e)
#define FQ_BYTES   32768
#define FKV_BYTES  65536
#define FSMEM_TOTAL (FQ_BYTES + 2 * FKV_BYTES)

__global__ __launch_bounds__(256)
void flash_hmma(const __nv_bfloat16* __restrict__ qh,
                const __nv_bfloat16* __restrict__ ql,
                __nv_bfloat16* __restrict__ ah,
                __nv_bfloat16* __restrict__ al)
{
    extern __shared__ __align__(128) char smem[];
    const uint32_t smb = smem_u32(smem);
    const int tid  = threadIdx.x;
    const int wid  = tid >> 5;
    const int lane = tid & 31;

    const int b  = blockIdx.z;
    const int h  = blockIdx.y;
    const int q0 = blockIdx.x * 128;

    // plane bases: qkv layout [token][3072], head h at col h*192 (+0 q, +64 k, +128 v)
    const size_t tok0 = (size_t)b * SEQ;
    const __nv_bfloat16* qh_base = qh + (tok0 + q0) * 3072 + h * 192;
    const __nv_bfloat16* ql_base = ql + (tok0 + q0) * 3072 + h * 192;
    const __nv_bfloat16* kh_base = qh + tok0 * 3072 + h * 192 + 64;
    const __nv_bfloat16* kl_base = ql + tok0 * 3072 + h * 192 + 64;
    const __nv_bfloat16* vh_base = qh + tok0 * 3072 + h * 192 + 128;
    const __nv_bfloat16* vl_base = ql + tok0 * 3072 + h * 192 + 128;

    // ---- issue Q planes (group 0) ----
    #pragma unroll
    for (int p = 0; p < 4; p++) {
        const int idx = tid + p * 256;     // 0..1023
        const int row = idx >> 3;
        const int c   = idx & 7;
        const uint32_t dst = smb + row * 128 + ((c ^ (row & 7)) << 4);
        CP_ASYNC16(dst,         (const void*)(qh_base + (size_t)row * 3072 + c * 8));
        CP_ASYNC16(dst + 16384, (const void*)(ql_base + (size_t)row * 3072 + c * 8));
    }
    CP_COMMIT();

    auto issueKV = [&](int buf, int j0) {
        const uint32_t bb = smb + FQ_BYTES + buf * FKV_BYTES;
        #pragma unroll
        for (int p = 0; p < 4; p++) {
            const int idx = tid + p * 256;
            const int row = idx >> 3;
            const int c   = idx & 7;
            const uint32_t dst = bb + row * 128 + ((c ^ (row & 7)) << 4);
            const size_t g = (size_t)(j0 + row) * 3072 + c * 8;
            CP_ASYNC16(dst,         (const void*)(kh_base + g));
            CP_ASYNC16(dst + 16384, (const void*)(kl_base + g));
            CP_ASYNC16(dst + 32768, (const void*)(vh_base + g));
            CP_ASYNC16(dst + 49152, (const void*)(vl_base + g));
        }
    };

    issueKV(0, 0);
    CP_COMMIT();

    // ---- wait Q (1 group may remain pending), build Q frags ----
    CP_WAIT1();
    __syncthreads();

    uint32_t qfh[4][4], qfl[4][4];
    {
        const int qrow = wid * 16 + (lane & 15);
        const int half = lane >> 4;
        #pragma unroll
        for (int kc = 0; kc < 4; kc++) {
            const int c = kc * 2 + half;
            const uint32_t ad = smb + qrow * 128 + ((c ^ (qrow & 7)) << 4);
            LDSM_X4(qfh[kc][0], qfh[kc][1], qfh[kc][2], qfh[kc][3], ad);
            LDSM_X4(qfl[kc][0], qfl[kc][1], qfl[kc][2], qfl[kc][3], ad + 16384);
        }
    }

    float o[8][4];
    #pragma unroll
    for (int i = 0; i < 8; i++)
        #pragma unroll
        for (int j = 0; j < 4; j++) o[i][j] = 0.0f;
    float M0 = -1e30f, M1 = -1e30f, L0 = 0.0f, L1 = 0.0f;

    const int NT = SEQ / 128;    // 16 key tiles
    for (int jt = 0; jt < NT; jt++) {
        if (jt + 1 < NT) {
            issueKV((jt + 1) & 1, (jt + 1) * 128);
            CP_COMMIT();
            CP_WAIT1();
        } else {
            CP_WAIT0();
        }
        __syncthreads();

        const uint32_t kb = smb + FQ_BYTES + (jt & 1) * FKV_BYTES;

        // ---- S = Q K^T (raw, scale folded into exp) ----
        float s[16][4];
        #pragma unroll
        for (int nt = 0; nt < 16; nt++)
            #pragma unroll
            for (int j = 0; j < 4; j++) s[nt][j] = 0.0f;

        const int bn   = (lane & 7) + ((lane >> 4) << 3);
        const int bhal = (lane >> 3) & 1;
        #pragma unroll
        for (int kc = 0; kc < 4; kc++) {
            #pragma unroll
            for (int ng = 0; ng < 8; ng++) {
                const int n = ng * 16 + bn;
                const int c = kc * 2 + bhal;
                const uint32_t ad = kb + n * 128 + ((c ^ (n & 7)) << 4);
                uint32_t h0, h1, h2, h3, l0, l1, l2, l3;
                LDSM_X4(h0, h1, h2, h3, ad);
                LDSM_X4(l0, l1, l2, l3, ad + 16384);
                MMA_BF16(s[2 * ng],     qfh[kc], h0, h1);
                MMA_BF16(s[2 * ng],     qfl[kc], h0, h1);
                MMA_BF16(s[2 * ng],     qfh[kc], l0, l1);
                MMA_BF16(s[2 * ng + 1], qfh[kc], h2, h3);
                MMA_BF16(s[2 * ng + 1], qfl[kc], h2, h3);
                MMA_BF16(s[2 * ng + 1], qfh[kc], l2, l3);
            }
        }

        // ---- online softmax (rows: g = lane>>2 and g+8) ----
        float mx0 = -1e30f, mx1 = -1e30f;
        #pragma unroll
        for (int nt = 0; nt < 16; nt++) {
            mx0 = fmaxf(mx0, fmaxf(s[nt][0], s[nt][1]));
            mx1 = fmaxf(mx1, fmaxf(s[nt][2], s[nt][3]));
        }
        mx0 = fmaxf(mx0, __shfl_xor_sync(0xffffffffu, mx0, 1));
        mx0 = fmaxf(mx0, __shfl_xor_sync(0xffffffffu, mx0, 2));
        mx1 = fmaxf(mx1, __shfl_xor_sync(0xffffffffu, mx1, 1));
        mx1 = fmaxf(mx1, __shfl_xor_sync(0xffffffffu, mx1, 2));
        const float Mn0 = fmaxf(M0, mx0);
        const float Mn1 = fmaxf(M1, mx1);
        const float a0 = ex2f((M0 - Mn0) * FSC);
        const float a1 = ex2f((M1 - Mn1) * FSC);
        M0 = Mn0; M1 = Mn1;
        const float c0 = Mn0 * FSC;
        const float c1 = Mn1 * FSC;

        float sum0 = 0.0f, sum1 = 0.0f;
        #pragma unroll
        for (int nt = 0; nt < 16; nt++) {
            s[nt][0] = ex2f(fmaf(s[nt][0], FSC, -c0));
            s[nt][1] = ex2f(fmaf(s[nt][1], FSC, -c0));
            s[nt][2] = ex2f(fmaf(s[nt][2], FSC, -c1));
            s[nt][3] = ex2f(fmaf(s[nt][3], FSC, -c1));
            sum0 += s[nt][0] + s[nt][1];
            sum1 += s[nt][2] + s[nt][3];
        }
        sum0 += __shfl_xor_sync(0xffffffffu, sum0, 1);
        sum0 += __shfl_xor_sync(0xffffffffu, sum0, 2);
        sum1 += __shfl_xor_sync(0xffffffffu, sum1, 1);
        sum1 += __shfl_xor_sync(0xffffffffu, sum1, 2);
        L0 = L0 * a0 + sum0;
        L1 = L1 * a1 + sum1;
        #pragma unroll
        for (int dt = 0; dt < 8; dt++) {
            o[dt][0] *= a0; o[dt][1] *= a0;
            o[dt][2] *= a1; o[dt][3] *= a1;
        }

        // ---- O += P V : P from s (split hi/lo in-register), V via ldmatrix.trans ----
        const int tq = lane >> 3;              // V tile quadrant
        const int vrow_in = ((tq & 1) << 3) + (lane & 7);
        #pragma unroll
        for (int kc2 = 0; kc2 < 8; kc2++) {
            const float* se = s[2 * kc2];
            const float* so = s[2 * kc2 + 1];
            uint32_t ph[4], pl[4];
            {
                __nv_bfloat162 t0 = __floats2bfloat162_rn(se[0], se[1]);
                float2 f0 = __bfloat1622float2(t0);
                __nv_bfloat162 u0 = __floats2bfloat162_rn(se[0] - f0.x, se[1] - f0.y);
                __nv_bfloat162 t1 = __floats2bfloat162_rn(se[2], se[3]);
                float2 f1 = __bfloat1622float2(t1);
                __nv_bfloat162 u1 = __floats2bfloat162_rn(se[2] - f1.x, se[3] - f1.y);
                __nv_bfloat162 t2 = __floats2bfloat162_rn(so[0], so[1]);
                float2 f2 = __bfloat1622float2(t2);
                __nv_bfloat162 u2 = __floats2bfloat162_rn(so[0] - f2.x, so[1] - f2.y);
                __nv_bfloat162 t3 = __floats2bfloat162_rn(so[2], so[3]);
                float2 f3 = __bfloat1622float2(t3);
                __nv_bfloat162 u3 = __floats2bfloat162_rn(so[2] - f3.x, so[3] - f3.y);
                ph[0] = *(uint32_t*)&t0; pl[0] = *(uint32_t*)&u0;
                ph[1] = *(uint32_t*)&t1; pl[1] = *(uint32_t*)&u1;
                ph[2] = *(uint32_t*)&t2; pl[2] = *(uint32_t*)&u2;
                ph[3] = *(uint32_t*)&t3; pl[3] = *(uint32_t*)&u3;
            }
            const int krow = kc2 * 16 + vrow_in;
            #pragma unroll
            for (int nd = 0; nd < 4; nd++) {
                const int c = nd * 2 + (tq >> 1);
                const uint32_t ad = kb + 32768 + krow * 128 + ((c ^ (krow & 7)) << 4);
                uint32_t v0, v1, v2, v3, u0, u1, u2, u3;
                LDSM_X4_T(v0, v1, v2, v3, ad);
                LDSM_X4_T(u0, u1, u2, u3, ad + 16384);
                MMA_BF16(o[nd * 2],     ph, v0, v1);
                MMA_BF16(o[nd * 2],     pl, v0, v1);
                MMA_BF16(o[nd * 2],     ph, u0, u1);
                MMA_BF16(o[nd * 2 + 1], ph, v2, v3);
                MMA_BF16(o[nd * 2 + 1], pl, v2, v3);
                MMA_BF16(o[nd * 2 + 1], ph, u2, u3);
            }
        }
        __syncthreads();
    }

    // ---- epilogue: normalize, write bf16 hi/lo planes of attn ----
    const float inv0 = __fdividef(1.0f, L0);
    const float inv1 = __fdividef(1.0f, L1);
    const int g   = lane >> 2;
    const int tig = lane & 3;
    const size_t row0 = tok0 + q0 + wid * 16 + g;
    #pragma unroll
    for (int nt = 0; nt < 8; nt++) {
        const int col = h * 64 + nt * 8 + tig * 2;
        {
            const float v0 = o[nt][0] * inv0;
            const float v1 = o[nt][1] * inv0;
            __nv_bfloat162 hh = __floats2bfloat162_rn(v0, v1);
            float2 hf = __bfloat1622float2(hh);
            __nv_bfloat162 ll = __floats2bfloat162_rn(v0 - hf.x, v1 - hf.y);
            *(__nv_bfloat162*)(ah + row0 * DMODEL + col) = hh;
            *(__nv_bfloat162*)(al + row0 * DMODEL + col) = ll;
        }
        {
            const float v0 = o[nt][2] * inv1;
            const float v1 = o[nt][3] * inv1;
            __nv_bfloat162 hh = __floats2bfloat162_rn(v0, v1);
            float2 hf = __bfloat1622float2(hh);
            __nv_bfloat162 ll = __floats2bfloat162_rn(v0 - hf.x, v1 - hf.y);
            *(__nv_bfloat162*)(ah + (row0 + 8) * DMODEL + col) = hh;
            *(__nv_bfloat162*)(al + (row0 + 8) * DMODEL + col) = ll;
        }
    }
}

// ---------------------------------------------------------------------------
// Launch
// ---------------------------------------------------------------------------
extern "C" void kernel_launch(void* const* d_in, const int* in_sizes, int n_in,
                              void* d_out, int out_size)
{
    const float* x    = (const float*)d_in[0];
    const float* Wqkv = (const float*)d_in[1];
    const float* bqkv = (const float*)d_in[2];
    const float* Wout = (const float*)d_in[3];
    const float* bout = (const float*)d_in[4];
    float* out = (float*)d_out;

    __nv_bfloat16 *xh, *xl, *qh, *ql, *ah, *al, *w1h, *w1l, *w2h, *w2l;
    cudaGetSymbolAddress((void**)&xh,  g_xh);
    cudaGetSymbolAddress((void**)&xl,  g_xl);
    cudaGetSymbolAddress((void**)&qh,  g_qh);
    cudaGetSymbolAddress((void**)&ql,  g_ql);
    cudaGetSymbolAddress((void**)&ah,  g_ah);
    cudaGetSymbolAddress((void**)&al,  g_al);
    cudaGetSymbolAddress((void**)&w1h, g_w1h);
    cudaGetSymbolAddress((void**)&w1l, g_w1l);
    cudaGetSymbolAddress((void**)&w2h, g_w2h);
    cudaGetSymbolAddress((void**)&w2l, g_w2l);

    cudaFuncSetAttribute(gemm_hmma, cudaFuncAttributeMaxDynamicSharedMemorySize,
                         HSMEM_TOTAL);
    cudaFuncSetAttribute(flash_hmma, cudaFuncAttributeMaxDynamicSharedMemorySize,
                         FSMEM_TOTAL);

    split_plain<<<(M_TOKENS * DMODEL) / (256 * 8), 256>>>(x, xh, xl);
    split_transpose<<<dim3(DMODEL / 32, QKVROW / 32), dim3(32, 8)>>>(
        Wqkv, w1h, w1l, DMODEL, QKVROW);
    split_transpose<<<dim3(DMODEL / 32, DMODEL / 32), dim3(32, 8)>>>(
        Wout, w2h, w2l, DMODEL, DMODEL);

    // 1) qkv planes = split(x @ Wqkv + bqkv)
    gemm_hmma<<<dim3(QKVROW / 128, M_TOKENS / 128), 256, HSMEM_TOTAL>>>(
        xh, xl, w1h, w1l, bqkv, nullptr, qh, ql, M_TOKENS, QKVROW, DMODEL, 1);

    // 2) flash attention -> attn planes
    flash_hmma<<<dim3(SEQ / 128, NHEADS, BATCH), 256, FSMEM_TOTAL>>>(
        qh, ql, ah, al);

    // 3) out = attn @ Wout + bout (fp32)
    gemm_hmma<<<dim3(DMODEL / 128, M_TOKENS / 128), 256, HSMEM_TOTAL>>>(
        ah, al, w2h, w2l, bout, out, nullptr, nullptr, M_TOKENS, DMODEL, DMODEL, 0);
}